// round 1
// baseline (speedup 1.0000x reference)
#include <cuda_runtime.h>
#include <math.h>

// Problem constants (fixed by setup_inputs)
#define BB 64      // batch
#define CC 256     // channels
#define DD 64      // 2D map side
#define TT 128     // total sentences (B * n, n = 2)
#define PP 2080    // triu proposals = D*(D+1)/2
#define TPL 64     // proposals per tile in main pass
#define NTILE 33   // ceil(PP / TPL)
#define NBLK (BB * NTILE)

// ---------------- scratch (device globals; fully overwritten every launch) ---
__device__ int   g_pos[PP];             // p -> r*64+c flat position in DxD
__device__ int   g_pk[TT];              // argmax p of iou2ds_f per t (K=1)
__device__ float g_qn[BB * CC];         // normalized query feats
__device__ float g_sn[TT * CC];         // normalized sentence feats
__device__ float g_norm2k[TT];          // |v[b', pos_k(t)]|^2
__device__ float g_cross[BB];           // vk0 . vk1 raw dot per b'
__device__ float g_sTop[TT * BB];       // cosine(topk_vf[t], qf_n[b])
__device__ float g_qs[BB * TT];         // qf_n[b] . sf_n[t']
__device__ float g_totQpart[NBLK * BB]; // per-block partial: sum_p exp(10 s[q, b', p])
__device__ float g_posQpart[NBLK];      // per-block partial: pos subset (q==b', iou>0.5)
__device__ float g_negIpart[NBLK * 2];  // per-block partial intra neg-sums (2 t's per b')

// ---------------- init: triu index map ----------------
__global__ void k_init() {
    int r = threadIdx.x;
    if (r < DD) {
        int start = r * DD - (r * (r - 1)) / 2;
        for (int j = 0; j < DD - r; j++) g_pos[start + j] = r * DD + r + j;
    }
}

// ---------------- row normalization (256 threads = C) ----------------
__device__ __forceinline__ float blk_sumsq(float v) {
    float s = v * v;
    for (int o = 16; o > 0; o >>= 1) s += __shfl_xor_sync(0xffffffffu, s, o);
    __shared__ float ws[8];
    int tid = threadIdx.x;
    if ((tid & 31) == 0) ws[tid >> 5] = s;
    __syncthreads();
    float tot = ws[0] + ws[1] + ws[2] + ws[3] + ws[4] + ws[5] + ws[6] + ws[7];
    return tot;
}

__global__ void k_norm_q(const float* __restrict__ q) {
    int row = blockIdx.x, tid = threadIdx.x;
    float v = q[row * CC + tid];
    float tot = blk_sumsq(v);
    float inv = 1.0f / fmaxf(sqrtf(tot), 1e-12f);
    g_qn[row * CC + tid] = v * inv;
}

__global__ void k_norm_s(const float* __restrict__ s) {
    int row = blockIdx.x, tid = threadIdx.x;
    float v = s[row * CC + tid];
    float tot = blk_sumsq(v);
    float inv = 1.0f / fmaxf(sqrtf(tot), 1e-12f);
    g_sn[row * CC + tid] = v * inv;
}

// ---------------- topk (K=1) over iou2ds_f, first-index tie-break ----------
__global__ void k_topk(const float* __restrict__ iou2ds) {
    int t = blockIdx.x, tid = threadIdx.x;
    float best = -1e30f; int bi = 0x3fffffff;
    for (int p = tid; p < PP; p += 256) {
        float v = iou2ds[t * (DD * DD) + g_pos[p]];
        if (v > best) { best = v; bi = p; }   // p increases -> keeps lowest idx on tie
    }
    __shared__ float bv[256]; __shared__ int bx[256];
    bv[tid] = best; bx[tid] = bi;
    __syncthreads();
    for (int s = 128; s > 0; s >>= 1) {
        if (tid < s) {
            if (bv[tid + s] > bv[tid] ||
                (bv[tid + s] == bv[tid] && bx[tid + s] < bx[tid])) {
                bv[tid] = bv[tid + s]; bx[tid] = bx[tid + s];
            }
        }
        __syncthreads();
    }
    if (tid == 0) g_pk[t] = bx[0];
}

// ---------------- per-b' topk-vector stats: norms + cross dot ----------------
__global__ void k_kstats(const float* __restrict__ vid) {
    int b = blockIdx.x, c = threadIdx.x;  // 256 threads
    int pk0 = g_pos[g_pk[2 * b]], pk1 = g_pos[g_pk[2 * b + 1]];
    const float* vb = vid + (size_t)b * CC * (DD * DD);
    float v0 = vb[(size_t)c * (DD * DD) + pk0];
    float v1 = vb[(size_t)c * (DD * DD) + pk1];
    float a = v0 * v0, d2 = v1 * v1, x = v0 * v1;
    for (int o = 16; o > 0; o >>= 1) {
        a  += __shfl_xor_sync(0xffffffffu, a, o);
        d2 += __shfl_xor_sync(0xffffffffu, d2, o);
        x  += __shfl_xor_sync(0xffffffffu, x, o);
    }
    __shared__ float sa[8], sd[8], sx[8];
    if ((c & 31) == 0) { sa[c >> 5] = a; sd[c >> 5] = d2; sx[c >> 5] = x; }
    __syncthreads();
    if (c == 0) {
        float ta = 0, td = 0, tc = 0;
        for (int w = 0; w < 8; w++) { ta += sa[w]; td += sd[w]; tc += sx[w]; }
        g_norm2k[2 * b] = ta; g_norm2k[2 * b + 1] = td; g_cross[b] = tc;
    }
}

// ---------------- qf_n @ sf_n^T (tiny) ----------------
__global__ void k_qs() {
    int b = blockIdx.x, tid = threadIdx.x;  // 256 threads
    __shared__ float qsh[CC];
    qsh[tid] = g_qn[b * CC + tid];
    __syncthreads();
    int w = tid >> 5, lane = tid & 31;
    for (int t2 = w; t2 < TT; t2 += 8) {
        float a = 0.f;
        for (int c = lane; c < CC; c += 32) a += qsh[c] * g_sn[t2 * CC + c];
        for (int o = 16; o > 0; o >>= 1) a += __shfl_xor_sync(0xffffffffu, a, o);
        if (lane == 0) g_qs[b * TT + t2] = a;
    }
}

// ---------------- main fused pass ----------------
// grid (NTILE, BB), 256 threads. Block = (proposal tile [p0, p0+64), video b').
// Phase A: norms + intra dots. Phase B: 64x64x256 GEMM vs qf_n.
// Epilogue: exp-sum partials (deterministic block reductions), sTop writes.
__global__ void __launch_bounds__(256) k_main(const float* __restrict__ vid,
                                              const float* __restrict__ iou2d) {
    int tileIdx = blockIdx.x, bp = blockIdx.y;
    int p0 = tileIdx * TPL;
    int tid = threadIdx.x;

    __shared__ __align__(16) float Vs[64][68];  // [k][p], 272B rows (16B aligned)
    __shared__ __align__(16) float Qs[64][68];  // [k][q]
    __shared__ float vk0s[CC], vk1s[CC];
    __shared__ int   posArr[TPL];
    __shared__ float ioul[TPL];
    __shared__ float n2s[TPL], i0s[TPL], i1s[TPL], invn[TPL];
    __shared__ float rbuf[16][64];
    __shared__ float redAll[256];

    const float* vb = vid + (size_t)bp * CC * (DD * DD);
    int t0 = 2 * bp, t1 = 2 * bp + 1;
    int pkI0 = g_pk[t0], pkI1 = g_pk[t1];
    int pk0 = g_pos[pkI0], pk1 = g_pos[pkI1];

    // preload topk vectors (strided; L2-resident across this b''s 33 blocks)
    vk0s[tid] = vb[(size_t)tid * (DD * DD) + pk0];
    vk1s[tid] = vb[(size_t)tid * (DD * DD) + pk1];
    if (tid < TPL) {
        int pg = p0 + tid;
        int pc = pg < PP ? pg : PP - 1;  // clamp for safe loads; masked later
        int pos = g_pos[pc];
        posArr[tid] = pos;
        ioul[tid] = iou2d[bp * (DD * DD) + pos];
    }
    __syncthreads();

    // ---- Phase A: norm2, v.vk0, v.vk1 per proposal ----
    {
        int p = tid & 63, kq = tid >> 6;
        const float* base = vb + posArr[p];
        float an = 0.f, a0 = 0.f, a1 = 0.f;
        int k0 = kq * 64;
        #pragma unroll 4
        for (int k = k0; k < k0 + 64; k++) {
            float v = base[(size_t)k * (DD * DD)];
            an += v * v; a0 += v * vk0s[k]; a1 += v * vk1s[k];
        }
        rbuf[kq][p] = an; rbuf[kq + 4][p] = a0; rbuf[kq + 8][p] = a1;
    }
    __syncthreads();
    if (tid < TPL) {
        float an = rbuf[0][tid] + rbuf[1][tid] + rbuf[2][tid] + rbuf[3][tid];
        float a0 = rbuf[4][tid] + rbuf[5][tid] + rbuf[6][tid] + rbuf[7][tid];
        float a1 = rbuf[8][tid] + rbuf[9][tid] + rbuf[10][tid] + rbuf[11][tid];
        n2s[tid] = an; i0s[tid] = a0; i1s[tid] = a1;
        invn[tid] = 1.0f / fmaxf(sqrtf(an), 1e-12f);
    }
    __syncthreads();

    // ---- Phase B: GEMM, C[p,q] = sum_k v[k,p] * qn[q,k] ----
    float acc[4][4] = {};
    int tx = tid & 15, ty = tid >> 4;
    for (int kc = 0; kc < 4; kc++) {
        for (int idx = tid; idx < 64 * 64; idx += 256) {
            int k = idx >> 6, p = idx & 63;
            Vs[k][p] = vb[(size_t)(kc * 64 + k) * (DD * DD) + posArr[p]];
        }
        for (int idx = tid; idx < 64 * 64; idx += 256) {
            int k = idx & 63, q = idx >> 6;
            Qs[k][q] = g_qn[q * CC + kc * 64 + k];
        }
        __syncthreads();
        #pragma unroll 8
        for (int k = 0; k < 64; k++) {
            float4 av = *(const float4*)(&Vs[k][tx * 4]);
            float4 bv = *(const float4*)(&Qs[k][ty * 4]);
            float a[4] = {av.x, av.y, av.z, av.w};
            float b[4] = {bv.x, bv.y, bv.z, bv.w};
            #pragma unroll
            for (int i = 0; i < 4; i++)
                #pragma unroll
                for (int j = 0; j < 4; j++)
                    acc[i][j] += a[i] * b[j];
        }
        __syncthreads();
    }

    // ---- Epilogue ----
    float tsum[4] = {0.f, 0.f, 0.f, 0.f};
    float posAcc = 0.f;
    #pragma unroll
    for (int i = 0; i < 4; i++) {
        int p = tx * 4 + i, pg = p0 + p;
        bool valid = pg < PP;
        float inv = invn[p];
        bool posm = valid && (ioul[p] > 0.5f);
        bool isT0 = (pg == pkI0), isT1 = (pg == pkI1);
        #pragma unroll
        for (int j = 0; j < 4; j++) {
            int q = ty * 4 + j;
            float s = acc[i][j] * inv;               // cosine (qn is unit)
            float e = valid ? __expf(10.0f * s) : 0.f;
            tsum[j] += e;
            if (q == bp && posm) posAcc += e;
            if (isT0) g_sTop[t0 * BB + q] = s;
            if (isT1) g_sTop[t1 * BB + q] = s;
        }
    }
    #pragma unroll
    for (int j = 0; j < 4; j++) rbuf[tx][ty * 4 + j] = tsum[j];
    redAll[tid] = posAcc;
    __syncthreads();

    int blk = bp * NTILE + tileIdx;
    if (tid < 64) {
        float s = 0.f;
        #pragma unroll
        for (int r = 0; r < 16; r++) s += rbuf[r][tid];
        g_totQpart[blk * BB + tid] = s;
    }
    for (int s = 128; s > 0; s >>= 1) {
        if (tid < s) redAll[tid] += redAll[tid + s];
        __syncthreads();
    }
    if (tid == 0) g_posQpart[blk] = redAll[0];
    __syncthreads();  // rbuf reads above finished before reuse below

    if (tid < 64) {
        int pg = p0 + tid;
        bool negm = (pg < PP) && (ioul[tid] < 0.5f);
        float invk0 = 1.0f / fmaxf(sqrtf(g_norm2k[t0]), 1e-12f);
        float invk1 = 1.0f / fmaxf(sqrtf(g_norm2k[t1]), 1e-12f);
        float s0 = i0s[tid] * invn[tid] * invk0;
        float s1 = i1s[tid] * invn[tid] * invk1;
        rbuf[0][tid] = negm ? __expf(10.0f * s0) : 0.f;
        rbuf[1][tid] = negm ? __expf(10.0f * s1) : 0.f;
    }
    __syncthreads();
    if (tid < 2) {
        float s = 0.f;
        for (int p = 0; p < 64; p++) s += rbuf[tid][p];
        g_negIpart[blk * 2 + tid] = s;
    }
}

// ---------------- final: assemble the 4 losses ----------------
__global__ void k_final(float* __restrict__ out) {
    __shared__ float totQ[BB], posQ[BB], negI[TT];
    __shared__ float red[TT];
    int tid = threadIdx.x;  // 128

    if (tid < BB) {
        float s = 0.f;
        for (int blk = 0; blk < NBLK; blk++) s += g_totQpart[blk * BB + tid];
        totQ[tid] = s;
        float sp = 0.f;
        for (int ti = 0; ti < NTILE; ti++) sp += g_posQpart[tid * NTILE + ti];
        posQ[tid] = sp;
    }
    {
        int b = tid >> 1, j = tid & 1;
        float s = 0.f;
        for (int ti = 0; ti < NTILE; ti++) s += g_negIpart[(b * NTILE + ti) * 2 + j];
        negI[tid] = s;
    }
    __syncthreads();

    int b = tid >> 1;  // scatter_idx[t] = t/2 (n=2 per video)
    // inter_video
    float pos = g_sTop[tid * BB + b];
    float pe = __expf(10.f * pos);
    float ns = 0.f;
    for (int q = 0; q < BB; q++)
        if (q != b) ns += __expf(10.f * g_sTop[tid * BB + q]);
    float l_iv = -(10.f * pos - logf(pe + ns));
    // inter_query (same pos, neg = total - pos-subset)
    float l_q = -(10.f * pos - logf(pe + (totQ[b] - posQ[b])));
    // intra_video: this t contributes (self, cross) entries
    float inv0 = 1.f / fmaxf(sqrtf(g_norm2k[2 * b]), 1e-12f);
    float inv1 = 1.f / fmaxf(sqrtf(g_norm2k[2 * b + 1]), 1e-12f);
    float crossn = g_cross[b] * inv0 * inv1;
    float invt = (tid & 1) ? inv1 : inv0;
    float selfn = g_norm2k[tid] * invt * invt;
    float nI = negI[tid];
    float l_ivd = -(10.f * selfn  - logf(__expf(10.f * selfn)  + nI))
                + -(10.f * crossn - logf(__expf(10.f * crossn) + nI));
    // intra_query
    float posq = g_qs[b * TT + tid];
    float nsq = 0.f;
    for (int t2 = 0; t2 < TT; t2++)
        if ((t2 >> 1) != b) nsq += __expf(10.f * g_qs[b * TT + t2]);
    float l_iq = -(10.f * posq - logf(__expf(10.f * posq) + nsq));

    float vals[4] = {l_iv, l_q, l_ivd, l_iq};
    float divi[4] = {128.f, 128.f, 256.f, 128.f};
    for (int m = 0; m < 4; m++) {
        red[tid] = vals[m];
        __syncthreads();
        for (int s = 64; s > 0; s >>= 1) {
            if (tid < s) red[tid] += red[tid + s];
            __syncthreads();
        }
        if (tid == 0) out[m] = red[0] / divi[m];
        __syncthreads();
    }
}

// ---------------- launch ----------------
extern "C" void kernel_launch(void* const* d_in, const int* in_sizes, int n_in,
                              void* d_out, int out_size) {
    const float* vid    = (const float*)d_in[0];  // (B, C, D, D)
    const float* qf     = (const float*)d_in[1];  // (B, C)
    const float* sf     = (const float*)d_in[2];  // (T, C)
    const float* iou2d  = (const float*)d_in[3];  // (B, D, D)
    const float* iou2ds = (const float*)d_in[4];  // (T, D, D)
    (void)in_sizes; (void)n_in; (void)out_size;

    k_init  <<<1, 64>>>();
    k_norm_q<<<BB, 256>>>(qf);
    k_norm_s<<<TT, 256>>>(sf);
    k_topk  <<<TT, 256>>>(iou2ds);
    k_kstats<<<BB, 256>>>(vid);
    k_qs    <<<BB, 256>>>();
    k_main  <<<dim3(NTILE, BB), 256>>>(vid, iou2d);
    k_final <<<1, 128>>>((float*)d_out);
}

// round 4
// speedup vs baseline: 1.4672x; 1.4672x over previous
#include <cuda_runtime.h>
#include <math.h>

// Problem constants (fixed by setup_inputs)
#define BB 64      // batch
#define CC 256     // channels
#define DD 64      // 2D map side
#define TT 128     // total sentences (B * n, n = 2)
#define PP 2080    // triu proposals = D*(D+1)/2
#define TPL 128    // proposals per tile in main pass
#define KCH 32     // K chunk
#define NKC (CC / KCH)
#define NTILE 17   // ceil(PP / TPL)
#define NBLK (BB * NTILE)

typedef unsigned long long u64;

// ---------------- scratch (device globals; fully overwritten every launch) ---
__device__ int   g_pk[TT];              // argmax p (triu order) per t (K=1)
__device__ int   g_pkflat[TT];          // same, flat r*64+c position
__device__ float g_qn[BB * CC];         // normalized query feats (row-major)
__device__ float g_qnT[CC * BB];        // normalized query feats (C-major)
__device__ float g_sn[TT * CC];         // normalized sentence feats
__device__ float g_norm2k[TT];          // |v[b', pos_k(t)]|^2
__device__ float g_cross[BB];           // vk0 . vk1 raw dot per b'
__device__ float g_sTop[TT * BB];       // cosine(topk_vf[t], qf_n[b])
__device__ float g_qs[BB * TT];         // qf_n[b] . sf_n[t']
__device__ float g_totQpart[NBLK * BB]; // per-block partial: sum_p exp(10 s[q,b',p])
__device__ float g_posQpart[NBLK];      // per-block partial: pos subset (q==b', iou>0.5)
__device__ float g_negIpart[NBLK * 2];  // per-block partial intra neg-sums

// ---------------- f32x2 helpers (b64 regs via "l" constraint) ----------------
__device__ __forceinline__ u64 pack2(float lo, float hi) {
    u64 d; asm("mov.b64 %0, {%1, %2};" : "=l"(d) : "f"(lo), "f"(hi)); return d;
}
__device__ __forceinline__ void ffma2(u64& acc, u64 a, u64 b) {
    asm("fma.rn.f32x2 %0, %1, %2, %0;" : "+l"(acc) : "l"(a), "l"(b));
}
__device__ __forceinline__ float2 unpack2(u64 d) {
    float2 f; asm("mov.b64 {%0, %1}, %2;" : "=f"(f.x), "=f"(f.y) : "l"(d)); return f;
}

// ---------------- topk (K=1), coalesced full-row read + triu mask ----------
__global__ void k_topk(const float* __restrict__ iou2ds) {
    int t = blockIdx.x, tid = threadIdx.x;
    const float4* row = (const float4*)(iou2ds + (size_t)t * (DD * DD));
    float best = -1e30f; int bf = 0x3fffffff;
    for (int v = tid; v < 1024; v += 256) {
        float4 x = row[v];
        int f0 = v * 4;
        float vals[4] = {x.x, x.y, x.z, x.w};
        #pragma unroll
        for (int e = 0; e < 4; e++) {
            int f = f0 + e, r = f >> 6, c = f & 63;
            if (c >= r && vals[e] > best) { best = vals[e]; bf = f; }
        }
    }
    __shared__ float bv[256]; __shared__ int bx[256];
    bv[tid] = best; bx[tid] = bf;
    __syncthreads();
    for (int s = 128; s > 0; s >>= 1) {
        if (tid < s) {
            if (bv[tid + s] > bv[tid] ||
                (bv[tid + s] == bv[tid] && bx[tid + s] < bx[tid])) {
                bv[tid] = bv[tid + s]; bx[tid] = bx[tid + s];
            }
        }
        __syncthreads();
    }
    if (tid == 0) {
        int f = bx[0], r = f >> 6, c = f & 63;
        g_pk[t] = r * 64 - (r * (r - 1)) / 2 + (c - r);  // triu-order index
        g_pkflat[t] = f;
    }
}

// ---------------- per-b' topk-vector stats: norms + cross dot ----------------
__global__ void k_kstats(const float* __restrict__ vid) {
    int b = blockIdx.x, c = threadIdx.x;  // 256 threads
    int pk0 = g_pkflat[2 * b], pk1 = g_pkflat[2 * b + 1];
    const float* vb = vid + (size_t)b * CC * (DD * DD);
    float v0 = vb[(size_t)c * (DD * DD) + pk0];
    float v1 = vb[(size_t)c * (DD * DD) + pk1];
    float a = v0 * v0, d2 = v1 * v1, x = v0 * v1;
    for (int o = 16; o > 0; o >>= 1) {
        a  += __shfl_xor_sync(0xffffffffu, a, o);
        d2 += __shfl_xor_sync(0xffffffffu, d2, o);
        x  += __shfl_xor_sync(0xffffffffu, x, o);
    }
    __shared__ float sa[8], sd[8], sx[8];
    if ((c & 31) == 0) { sa[c >> 5] = a; sd[c >> 5] = d2; sx[c >> 5] = x; }
    __syncthreads();
    if (c == 0) {
        float ta = 0, td = 0, tc = 0;
        for (int w = 0; w < 8; w++) { ta += sa[w]; td += sd[w]; tc += sx[w]; }
        g_norm2k[2 * b] = ta; g_norm2k[2 * b + 1] = td; g_cross[b] = tc;
    }
}

// ---------------- row normalization (256 threads = C) ----------------
__device__ __forceinline__ float blk_sumsq(float v) {
    float s = v * v;
    for (int o = 16; o > 0; o >>= 1) s += __shfl_xor_sync(0xffffffffu, s, o);
    __shared__ float ws[8];
    int tid = threadIdx.x;
    if ((tid & 31) == 0) ws[tid >> 5] = s;
    __syncthreads();
    return ws[0] + ws[1] + ws[2] + ws[3] + ws[4] + ws[5] + ws[6] + ws[7];
}

__global__ void k_norm_q(const float* __restrict__ q) {
    int row = blockIdx.x, tid = threadIdx.x;
    float v = q[row * CC + tid];
    float inv = 1.0f / fmaxf(sqrtf(blk_sumsq(v)), 1e-12f);
    float nv = v * inv;
    g_qn[row * CC + tid] = nv;
    g_qnT[tid * BB + row] = nv;
}

__global__ void k_norm_s(const float* __restrict__ s) {
    int row = blockIdx.x, tid = threadIdx.x;
    float v = s[row * CC + tid];
    float inv = 1.0f / fmaxf(sqrtf(blk_sumsq(v)), 1e-12f);
    g_sn[row * CC + tid] = v * inv;
}

// ---------------- main fused pass ----------------
// grid (NTILE, BB), 256 threads. Block = (128-proposal tile, video b').
// Single gather of video; GEMM via packed fma.rn.f32x2; fused norm/intra dots.
__global__ void __launch_bounds__(256) k_main(const float* __restrict__ vid,
                                              const float* __restrict__ iou2d) {
    int tileIdx = blockIdx.x, bp = blockIdx.y;
    int p0 = tileIdx * TPL;
    int tid = threadIdx.x;

    __shared__ __align__(16) float Vs[KCH][TPL + 4];  // 32 x 132 (rows 528B, 16B-mult)
    __shared__ __align__(16) float Qs[KCH][BB + 4];   // 32 x 68
    __shared__ float vk0s[CC], vk1s[CC];
    __shared__ int   posArr[TPL];
    __shared__ float ioul[TPL];
    __shared__ float invn[TPL], i0s[TPL], i1s[TPL];
    __shared__ float statA[256], stat0[256], stat1[256];
    __shared__ float rbuf[16][64];
    __shared__ float redAll[256];

    const float* vb = vid + (size_t)bp * CC * (DD * DD);
    int t0 = 2 * bp, t1 = t0 + 1;
    int pkI0 = g_pk[t0], pkI1 = g_pk[t1];
    int pf0 = g_pkflat[t0], pf1 = g_pkflat[t1];

    vk0s[tid] = vb[(size_t)tid * (DD * DD) + pf0];
    vk1s[tid] = vb[(size_t)tid * (DD * DD) + pf1];
    if (tid < TPL) {
        int pg = p0 + tid;
        int pc = pg < PP ? pg : PP - 1;  // clamp; masked in epilogue
        int r = (int)(64.5f - sqrtf(64.5f * 64.5f - 2.0f * (float)pc));
        while (r > 0  && r * 64 - (r * (r - 1)) / 2 > pc) r--;
        while (r < 63 && (r + 1) * 64 - ((r + 1) * r) / 2 <= pc) r++;
        int start = r * 64 - (r * (r - 1)) / 2;
        int c = r + (pc - start);
        int pos = r * 64 + c;
        posArr[tid] = pos;
        ioul[tid] = iou2d[bp * (DD * DD) + pos];
    }
    __syncthreads();

    // register tile: 8p x 4q per thread; p pairs packed in f32x2
    int px = tid >> 4;      // 0..15 -> p base px*8
    int qy = tid & 15;      // 0..15 -> q base qy*4
    int pS = tid & 127;     // stats: own proposal
    int kh = tid >> 7;      // stats: k half
    u64 acc[4][4] = {};     // [j][pair]; 0 bits == (0.f, 0.f)
    float an = 0.f, a0 = 0.f, a1 = 0.f;

    for (int kc = 0; kc < NKC; kc++) {
        #pragma unroll
        for (int i = 0; i < 16; i++) {       // 32x128 V tile
            int idx = tid + i * 256, k = idx >> 7, p = idx & 127;
            Vs[k][p] = vb[(kc * KCH + k) * (DD * DD) + posArr[p]];
        }
        #pragma unroll
        for (int i = 0; i < 8; i++) {        // 32x64 Q tile (C-major global)
            int idx = tid + i * 256, k = idx >> 6, q = idx & 63;
            Qs[k][q] = g_qnT[(kc * KCH + k) * BB + q];
        }
        __syncthreads();

        // fused stats: 16 k per thread from shared
        #pragma unroll
        for (int kk = 0; kk < 16; kk++) {
            int k = kh * 16 + kk;
            float v = Vs[k][pS];
            an += v * v;
            a0 += v * vk0s[kc * KCH + k];
            a1 += v * vk1s[kc * KCH + k];
        }

        // GEMM: C[p,q] += sum_k V[k,p] * Q[k,q]
        #pragma unroll 8
        for (int k = 0; k < KCH; k++) {
            ulonglong2 aA = *(const ulonglong2*)&Vs[k][px * 8];
            ulonglong2 aB = *(const ulonglong2*)&Vs[k][px * 8 + 4];
            float4 bq = *(const float4*)&Qs[k][qy * 4];
            u64 b0 = pack2(bq.x, bq.x), b1 = pack2(bq.y, bq.y);
            u64 b2 = pack2(bq.z, bq.z), b3 = pack2(bq.w, bq.w);
            ffma2(acc[0][0], aA.x, b0); ffma2(acc[0][1], aA.y, b0);
            ffma2(acc[0][2], aB.x, b0); ffma2(acc[0][3], aB.y, b0);
            ffma2(acc[1][0], aA.x, b1); ffma2(acc[1][1], aA.y, b1);
            ffma2(acc[1][2], aB.x, b1); ffma2(acc[1][3], aB.y, b1);
            ffma2(acc[2][0], aA.x, b2); ffma2(acc[2][1], aA.y, b2);
            ffma2(acc[2][2], aB.x, b2); ffma2(acc[2][3], aB.y, b2);
            ffma2(acc[3][0], aA.x, b3); ffma2(acc[3][1], aA.y, b3);
            ffma2(acc[3][2], aB.x, b3); ffma2(acc[3][3], aB.y, b3);
        }
        __syncthreads();
    }

    // combine stats halves
    statA[tid] = an; stat0[tid] = a0; stat1[tid] = a1;
    __syncthreads();
    if (tid < TPL) {
        float n2 = statA[tid] + statA[tid + 128];
        invn[tid] = 1.0f / fmaxf(sqrtf(n2), 1e-12f);
        i0s[tid] = stat0[tid] + stat0[tid + 128];
        i1s[tid] = stat1[tid] + stat1[tid + 128];
    }
    __syncthreads();

    // epilogue: scores, exps, partial sums
    float tsum[4] = {0.f, 0.f, 0.f, 0.f};
    float posAcc = 0.f;
    int qbase = qy * 4;
    #pragma unroll
    for (int i = 0; i < 4; i++) {
        #pragma unroll
        for (int h = 0; h < 2; h++) {
            int p = px * 8 + 2 * i + h;
            int pg = p0 + p;
            bool valid = pg < PP;
            float inv = invn[p];
            bool posm = valid && (ioul[p] > 0.5f);
            bool is0 = (pg == pkI0), is1 = (pg == pkI1);
            #pragma unroll
            for (int j = 0; j < 4; j++) {
                float2 u = unpack2(acc[j][i]);
                float s = (h ? u.y : u.x) * inv;
                float e = valid ? __expf(10.0f * s) : 0.f;
                tsum[j] += e;
                if ((qbase + j) == bp && posm) posAcc += e;
                if (is0) g_sTop[t0 * BB + qbase + j] = s;
                if (is1) g_sTop[t1 * BB + qbase + j] = s;
            }
        }
    }
    #pragma unroll
    for (int j = 0; j < 4; j++) rbuf[px][qbase + j] = tsum[j];
    redAll[tid] = posAcc;
    __syncthreads();

    int blk = bp * NTILE + tileIdx;
    if (tid < 64) {
        float s = 0.f;
        #pragma unroll
        for (int r = 0; r < 16; r++) s += rbuf[r][tid];
        g_totQpart[blk * BB + tid] = s;
    }
    for (int s = 128; s > 0; s >>= 1) {
        if (tid < s) redAll[tid] += redAll[tid + s];
        __syncthreads();
    }
    if (tid == 0) g_posQpart[blk] = redAll[0];
    __syncthreads();

    if (tid < TPL) {
        int pg = p0 + tid;
        bool negm = (pg < PP) && (ioul[tid] < 0.5f);
        float invk0 = 1.0f / fmaxf(sqrtf(g_norm2k[t0]), 1e-12f);
        float invk1 = 1.0f / fmaxf(sqrtf(g_norm2k[t1]), 1e-12f);
        statA[tid] = negm ? __expf(10.0f * i0s[tid] * invn[tid] * invk0) : 0.f;
        stat0[tid] = negm ? __expf(10.0f * i1s[tid] * invn[tid] * invk1) : 0.f;
    }
    __syncthreads();
    if (tid < 2) {
        const float* src = tid ? stat0 : statA;
        float s = 0.f;
        for (int p = 0; p < TPL; p++) s += src[p];
        g_negIpart[blk * 2 + tid] = s;
    }
}

// ---------------- qf_n @ sf_n^T (tiny) ----------------
__global__ void k_qs() {
    int b = blockIdx.x, tid = threadIdx.x;  // 256 threads
    __shared__ float qsh[CC];
    qsh[tid] = g_qn[b * CC + tid];
    __syncthreads();
    int w = tid >> 5, lane = tid & 31;
    for (int t2 = w; t2 < TT; t2 += 8) {
        float a = 0.f;
        for (int c = lane; c < CC; c += 32) a += qsh[c] * g_sn[t2 * CC + c];
        for (int o = 16; o > 0; o >>= 1) a += __shfl_xor_sync(0xffffffffu, a, o);
        if (lane == 0) g_qs[b * TT + t2] = a;
    }
}

// ---------------- final: assemble the 4 losses ----------------
__global__ void k_final(float* __restrict__ out) {
    __shared__ float totQ4[BB][4];
    __shared__ float totQ[BB], posQ[BB], negI[TT];
    __shared__ float red[256];
    int tid = threadIdx.x;  // 256

    {   // totQ: 4-way split over the 1088 blocks
        int q = tid >> 2, part = tid & 3;
        float s = 0.f;
        for (int blk = part; blk < NBLK; blk += 4) s += g_totQpart[blk * BB + q];
        totQ4[q][part] = s;
    }
    if (tid < BB) {
        float sp = 0.f;
        for (int ti = 0; ti < NTILE; ti++) sp += g_posQpart[tid * NTILE + ti];
        posQ[tid] = sp;
    }
    if (tid < TT) {
        int b = tid >> 1, j = tid & 1;
        float s = 0.f;
        for (int ti = 0; ti < NTILE; ti++) s += g_negIpart[(b * NTILE + ti) * 2 + j];
        negI[tid] = s;
    }
    __syncthreads();
    if (tid < BB) totQ[tid] = totQ4[tid][0] + totQ4[tid][1] + totQ4[tid][2] + totQ4[tid][3];
    __syncthreads();

    float vals[4] = {0.f, 0.f, 0.f, 0.f};
    if (tid < TT) {
        int b = tid >> 1;  // scatter_idx[t] = t/2
        // inter_video
        float pos = g_sTop[tid * BB + b];
        float pe = __expf(10.f * pos);
        float ns = 0.f;
        for (int q = 0; q < BB; q++)
            if (q != b) ns += __expf(10.f * g_sTop[tid * BB + q]);
        vals[0] = -(10.f * pos - logf(pe + ns));
        // inter_query (neg = total - pos-subset)
        vals[1] = -(10.f * pos - logf(pe + (totQ[b] - posQ[b])));
        // intra_video
        float inv0 = 1.f / fmaxf(sqrtf(g_norm2k[2 * b]), 1e-12f);
        float inv1 = 1.f / fmaxf(sqrtf(g_norm2k[2 * b + 1]), 1e-12f);
        float crossn = g_cross[b] * inv0 * inv1;
        float invt = (tid & 1) ? inv1 : inv0;
        float selfn = g_norm2k[tid] * invt * invt;
        float nI = negI[tid];
        vals[2] = -(10.f * selfn  - logf(__expf(10.f * selfn)  + nI))
                + -(10.f * crossn - logf(__expf(10.f * crossn) + nI));
        // intra_query
        float posq = g_qs[b * TT + tid];
        float nsq = 0.f;
        for (int t2 = 0; t2 < TT; t2++)
            if ((t2 >> 1) != b) nsq += __expf(10.f * g_qs[b * TT + t2]);
        vals[3] = -(10.f * posq - logf(__expf(10.f * posq) + nsq));
    }
    const float divi[4] = {128.f, 128.f, 256.f, 128.f};
    for (int m = 0; m < 4; m++) {
        red[tid] = vals[m];
        __syncthreads();
        for (int s = 128; s > 0; s >>= 1) {
            if (tid < s) red[tid] += red[tid + s];
            __syncthreads();
        }
        if (tid == 0) out[m] = red[0] / divi[m];
        __syncthreads();
    }
}

// ---------------- launch ----------------
// Order chosen so ncu's skip-window lands on k_main (4th app launch).
extern "C" void kernel_launch(void* const* d_in, const int* in_sizes, int n_in,
                              void* d_out, int out_size) {
    const float* vid    = (const float*)d_in[0];  // (B, C, D, D)
    const float* qf     = (const float*)d_in[1];  // (B, C)
    const float* sf     = (const float*)d_in[2];  // (T, C)
    const float* iou2d  = (const float*)d_in[3];  // (B, D, D)
    const float* iou2ds = (const float*)d_in[4];  // (T, D, D)
    (void)in_sizes; (void)n_in; (void)out_size;

    k_topk  <<<TT, 256>>>(iou2ds);
    k_kstats<<<BB, 256>>>(vid);
    k_norm_q<<<BB, 256>>>(qf);
    k_main  <<<dim3(NTILE, BB), 256>>>(vid, iou2d);
    k_norm_s<<<TT, 256>>>(sf);
    k_qs    <<<BB, 256>>>();
    k_final <<<1, 256>>>((float*)d_out);
}